// round 16
// baseline (speedup 1.0000x reference)
#include <cuda_runtime.h>
#include <cuda_bf16.h>

// JointBilateral upsample, S=4, K=5. Best-measured skeleton (R10: 1024 blocks
// x 128 threads, 8 px/thread = rows {4p+gsel, 4p+gsel+2} x 4 cols, no smem,
// no barrier) + packed f32x2 tap math (column pairs (r0,r1)/(r2,r3) as one
// 64-bit lane) + free first tap for gsel=1 (its rowA IS guidance row 4p+1).
// Col/corner taps (r=3 only) scalar; divides on MUFU.

#define CH  (512 * 512)
#define E1  0.9950124791926823f   /* exp(-0.005) */
#define E4  0.9801986733067553f   /* exp(-0.020) */

typedef unsigned long long u64;

__device__ __forceinline__ u64 pk2(float lo, float hi)
{
    u64 r; asm("mov.b64 %0, {%1,%2};" : "=l"(r) : "f"(lo), "f"(hi)); return r;
}
__device__ __forceinline__ void up2(u64 v, float& lo, float& hi)
{
    asm("mov.b64 {%0,%1}, %2;" : "=f"(lo), "=f"(hi) : "l"(v));
}
__device__ __forceinline__ u64 fma2(u64 a, u64 b, u64 c)
{
    u64 d; asm("fma.rn.f32x2 %0, %1, %2, %3;" : "=l"(d) : "l"(a), "l"(b), "l"(c)); return d;
}
__device__ __forceinline__ u64 add2(u64 a, u64 b)
{
    u64 d; asm("add.rn.f32x2 %0, %1, %2;" : "=l"(d) : "l"(a), "l"(b)); return d;
}
__device__ __forceinline__ u64 mul2(u64 a, u64 b)
{
    u64 d; asm("mul.rn.f32x2 %0, %1, %2;" : "=l"(d) : "l"(a), "l"(b)); return d;
}

// exp(-0.125*s) for s in [0, 0.75]: cubic, 0.125 folded into coefficients
#define PC1 (-0.125f)
#define PC2 (0.0078125f)
#define PC3 (-3.2552083e-4f)

__device__ __forceinline__ float exp_s(float s)
{
    float p = fmaf(PC3, s, PC2);
    p = fmaf(p, s, PC1);
    return fmaf(p, s, 1.0f);
}

__global__ void __launch_bounds__(128) jb_kernel(
    const float* __restrict__ x,
    const float* __restrict__ g,
    const float* __restrict__ wgt,
    float* __restrict__ out)
{
    int tid  = threadIdx.x;
    int ql   = tid & 63;
    int gsel = tid >> 6;              // 0: rows {0,2}; 1: rows {1,3}
    int blk  = blockIdx.x;            // 1024 = 2 qh * 128 p * 4 b
    int qh   = blk & 1;
    int p    = (blk >> 1) & 127;
    int b    = blk >> 8;
    int q    = qh * 64 + ql;

    const float* gb = g + (size_t)b * 3 * CH;
    const float* xb = x + b * (128 * 128);

    bool row2 = (p < 127);
    bool col2 = (q < 127);
    int dq = col2 ? 4 : 0;
    int cq = col2 ? 1 : 0;

    int rowA = (4 * p + gsel) * 512 + 4 * q;
    int rowB = rowA + 2 * 512;
    int o00  = (4 * p + 1) * 512 + 4 * q + 1;

    // ---- front-loaded loads ----
    float4 a0 = *(const float4*)(gb + rowA);
    float4 a1 = *(const float4*)(gb + CH + rowA);
    float4 a2 = *(const float4*)(gb + 2 * CH + rowA);
    float4 e0 = *(const float4*)(gb + rowB);
    float4 e1 = *(const float4*)(gb + CH + rowB);
    float4 e2 = *(const float4*)(gb + 2 * CH + rowB);

    // first tap: gsel==1 already has it (rowA == guidance row 4p+1, col 4q+1 = .y)
    float t0, t1, t2;
    if (gsel == 1) {
        t0 = a0.y; t1 = a1.y; t2 = a2.y;
    } else {
        t0 = gb[o00];
        t1 = gb[o00 + CH];
        t2 = gb[o00 + 2 * CH];
    }
    float u0 = gb[o00 + dq];
    float u1 = gb[o00 + dq + CH];
    float u2 = gb[o00 + dq + 2 * CH];

    int xo = p * 128 + q;
    float x00 = xb[xo];
    float x01 = xb[xo + cq];

    float v0 = 0.f, v1 = 0.f, v2 = 0.f, zc0 = 0.f, zc1 = 0.f, zc2 = 0.f;
    float x10 = 0.f, x11 = 0.f;
    if (gsel == 1) {                  // warp-uniform
        int dr = row2 ? 4 * 512 : 0;
        v0 = gb[o00 + dr];
        v1 = gb[o00 + dr + CH];
        v2 = gb[o00 + dr + 2 * CH];
        zc0 = gb[o00 + dr + dq];
        zc1 = gb[o00 + dr + dq + CH];
        zc2 = gb[o00 + dr + dq + 2 * CH];
        int cp = row2 ? 1 : 0;
        x10 = xb[xo + cp * 128];
        x11 = xb[xo + cp * 128 + cq];
    }

    // packed constants / broadcasts
    const u64 NEG1 = pk2(-1.0f, -1.0f);
    const u64 ONE2 = pk2(1.0f, 1.0f);
    const u64 C1v  = pk2(PC1, PC1);
    const u64 C2v  = pk2(PC2, PC2);
    const u64 C3v  = pk2(PC3, PC3);
    u64 T0 = pk2(t0, t0), T1 = pk2(t1, t1), T2 = pk2(t2, t2);

    size_t obase = (size_t)b * CH;

    float espSA = (gsel == 1) ? 1.0f : E1;   // rowA: sp = gsel
    float espSB = (gsel == 1) ? E4 : E1;     // rowB: sp = gsel + 2

#pragma unroll
    for (int half = 0; half < 2; half++) {
        float4 c0 = (half == 0) ? a0 : e0;
        float4 c1 = (half == 0) ? a1 : e1;
        float4 c2 = (half == 0) ? a2 : e2;
        float espS = (half == 0) ? espSA : espSB;
        int sp = (half == 0) ? gsel : gsel + 2;
        const float* wr = wgt + (sp + 1) * 5;
        int orow = (half == 0) ? rowA : rowB;

        u64 C0a = pk2(c0.x, c0.y), C0b = pk2(c0.z, c0.w);
        u64 C1a = pk2(c1.x, c1.y), C1b = pk2(c1.z, c1.w);
        u64 C2a = pk2(c2.x, c2.y), C2b = pk2(c2.z, c2.w);

        u64 WXa = pk2(wr[1] * x00, wr[2] * x00);
        u64 WXb = pk2(wr[3] * x00, wr[4] * x00);
        u64 ESPa = pk2(espS * E1, espS);
        u64 ESPb = pk2(espS * E1, espS * E4);

        // ---- first tap, pair a (r0,r1) ----
        u64 d0 = fma2(C0a, NEG1, T0);
        u64 d1 = fma2(C1a, NEG1, T1);
        u64 d2 = fma2(C2a, NEG1, T2);
        u64 sA = mul2(d0, d0);
        sA = fma2(d1, d1, sA);
        sA = fma2(d2, d2, sA);
        u64 pA = fma2(C3v, sA, C2v);
        pA = fma2(pA, sA, C1v);
        pA = fma2(pA, sA, ONE2);
        u64 eA = mul2(pA, ESPa);
        u64 denA = eA;
        u64 numA = mul2(eA, WXa);

        // ---- first tap, pair b (r2,r3) ----
        d0 = fma2(C0b, NEG1, T0);
        d1 = fma2(C1b, NEG1, T1);
        d2 = fma2(C2b, NEG1, T2);
        u64 sB = mul2(d0, d0);
        sB = fma2(d1, d1, sB);
        sB = fma2(d2, d2, sB);
        u64 pB = fma2(C3v, sB, C2v);
        pB = fma2(pB, sB, C1v);
        pB = fma2(pB, sB, ONE2);
        u64 eB = mul2(pB, ESPb);
        u64 denB = eB;
        u64 numB = mul2(eB, WXb);

        if (gsel == 1 && half == 1 && row2) {   // row 4p+3: second-row taps
            u64 V0 = pk2(v0, v0), V1 = pk2(v1, v1), V2 = pk2(v2, v2);
            u64 WX2a = pk2(wgt[1] * x10, wgt[2] * x10);
            u64 WX2b = pk2(wgt[3] * x10, wgt[4] * x10);
            u64 ESP2a = pk2(E4 * E1, E4);
            u64 ESP2b = pk2(E4 * E1, E4 * E4);

            u64 f0 = fma2(C0a, NEG1, V0);
            u64 f1 = fma2(C1a, NEG1, V1);
            u64 f2 = fma2(C2a, NEG1, V2);
            u64 s2 = mul2(f0, f0);
            s2 = fma2(f1, f1, s2);
            s2 = fma2(f2, f2, s2);
            u64 p2 = fma2(C3v, s2, C2v);
            p2 = fma2(p2, s2, C1v);
            p2 = fma2(p2, s2, ONE2);
            u64 e2p = mul2(p2, ESP2a);
            denA = add2(denA, e2p);
            numA = fma2(e2p, WX2a, numA);

            f0 = fma2(C0b, NEG1, V0);
            f1 = fma2(C1b, NEG1, V1);
            f2 = fma2(C2b, NEG1, V2);
            s2 = mul2(f0, f0);
            s2 = fma2(f1, f1, s2);
            s2 = fma2(f2, f2, s2);
            p2 = fma2(C3v, s2, C2v);
            p2 = fma2(p2, s2, C1v);
            p2 = fma2(p2, s2, ONE2);
            e2p = mul2(p2, ESP2b);
            denB = add2(denB, e2p);
            numB = fma2(e2p, WX2b, numB);
        }

        float den0, den1, den2f, den3, num0, num1, num2f, num3;
        up2(denA, den0, den1);
        up2(numA, num0, num1);
        up2(denB, den2f, den3);
        up2(numB, num2f, num3);

        if (col2) {   // second-col tap for r=3 (scalar)
            float h0 = u0 - c0.w;
            float h1 = u1 - c1.w;
            float h2 = u2 - c2.w;
            float sc = fmaf(h0, h0, fmaf(h1, h1, h2 * h2));
            float e3 = exp_s(sc) * (espS * E4);
            den3 += e3;
            num3 = fmaf(e3, wr[0] * x01, num3);

            if (gsel == 1 && half == 1 && row2) {   // corner tap
                float k0 = zc0 - c0.w;
                float k1 = zc1 - c1.w;
                float k2 = zc2 - c2.w;
                float sk = fmaf(k0, k0, fmaf(k1, k1, k2 * k2));
                float e4x = exp_s(sk) * (E4 * E4);
                den3 += e4x;
                num3 = fmaf(e4x, wgt[0] * x11, num3);
            }
        }

        float4 o = make_float4(__fdividef(num0, den0),
                               __fdividef(num1, den1),
                               __fdividef(num2f, den2f),
                               __fdividef(num3, den3));
        *(float4*)(out + obase + orow) = o;
    }
}

extern "C" void kernel_launch(void* const* d_in, const int* in_sizes, int n_in,
                              void* d_out, int out_size)
{
    const float* x   = (const float*)d_in[0];
    const float* g   = (const float*)d_in[1];
    const float* wgt = (const float*)d_in[2];
    float* out = (float*)d_out;

    // 1024 blocks: 2 qh * 128 p * 4 b ; 128 threads: 2 row-groups * 64 q
    jb_kernel<<<1024, 128>>>(x, g, wgt, out);
}